// round 1
// baseline (speedup 1.0000x reference)
#include <cuda_runtime.h>
#include <cuda_bf16.h>
#include <math.h>

// ---------------------------------------------------------------------------
// EfficientMoEMLPBlock — expert-choice MoE MLP
//   E=48 experts, S=4 shards, D=1024, M=1024, K=D/S=256, T=16384, cap=512
// Pipeline: router logits -> per-expert top-512 (radix select) + softmax ->
//           gather -> GEMM1+GELU -> GEMM2 * w -> scatter-add
// Round 0: fp32 SIMT GEMMs using packed fma.rn.f32x2 (FFMA2).
// ---------------------------------------------------------------------------

#define T_TOK   16384
#define D_DIM   1024
#define E_EXP   48
#define S_SHARD 4
#define M_DIM   1024
#define K_DIM   256
#define CAP     512

// ------------------------- scratch (device globals) ------------------------
__device__ float g_logits[(size_t)E_EXP * T_TOK];                    // [E][T]
__device__ int   g_idx[E_EXP * CAP];                                 // [E][cap]
__device__ float g_w[E_EXP * CAP];                                   // [E][cap]
__device__ float g_xg[(size_t)E_EXP * CAP * D_DIM];                  // [E][cap][D]
__device__ float g_h[(size_t)E_EXP * S_SHARD * CAP * M_DIM];         // [E*S][cap][M]

// ------------------------------- helpers -----------------------------------
__device__ __forceinline__ unsigned fkey(float f) {
    unsigned u = __float_as_uint(f);
    return (u & 0x80000000u) ? ~u : (u | 0x80000000u);
}

__device__ __forceinline__ unsigned long long pack2(float lo, float hi) {
    unsigned long long r;
    asm("mov.b64 %0, {%1, %2};" : "=l"(r) : "f"(lo), "f"(hi));
    return r;
}
__device__ __forceinline__ unsigned long long fma2(unsigned long long a,
                                                   unsigned long long b,
                                                   unsigned long long c) {
    unsigned long long d;
    asm("fma.rn.f32x2 %0, %1, %2, %3;" : "=l"(d) : "l"(a), "l"(b), "l"(c));
    return d;
}
__device__ __forceinline__ float lo2(unsigned long long v) {
    return __uint_as_float((unsigned)(v & 0xffffffffull));
}
__device__ __forceinline__ float hi2(unsigned long long v) {
    return __uint_as_float((unsigned)(v >> 32));
}
__device__ __forceinline__ float gelu_f(float v) {
    return 0.5f * v * (1.0f + erff(v * 0.70710678118654752440f));
}

// ------------------------------ zero out -----------------------------------
__global__ void zero_kernel(float4* __restrict__ p, int n4) {
    int i = blockIdx.x * blockDim.x + threadIdx.x;
    if (i < n4) p[i] = make_float4(0.f, 0.f, 0.f, 0.f);
}

// ------------------------- router logits [E][T] ----------------------------
// block: 128 tokens x 48 experts, 256 threads; thread: 4 tokens x 6 experts.
__global__ __launch_bounds__(256) void router_kernel(const float* __restrict__ x,
                                                     const float* __restrict__ Wr) {
    __shared__ float xs[32][129];  // [k][token]
    __shared__ float ws[32][49];   // [k][expert]
    const int tid = threadIdx.x;
    const int tb  = blockIdx.x * 128;
    const int t0  = (tid & 31) * 4;
    const int e0  = (tid >> 5) * 6;

    float acc[4][6];
#pragma unroll
    for (int i = 0; i < 4; i++)
#pragma unroll
        for (int j = 0; j < 6; j++) acc[i][j] = 0.f;

    for (int kb = 0; kb < D_DIM; kb += 32) {
        __syncthreads();
        for (int i = tid; i < 128 * 32; i += 256) {
            int r = i >> 5, c = i & 31;
            xs[c][r] = x[(size_t)(tb + r) * D_DIM + kb + c];
        }
        for (int i = tid; i < E_EXP * 32; i += 256) {
            int r = i >> 5, c = i & 31;
            ws[c][r] = Wr[(size_t)r * D_DIM + kb + c];
        }
        __syncthreads();
#pragma unroll 8
        for (int kk = 0; kk < 32; kk++) {
            float xv[4], wv[6];
#pragma unroll
            for (int i = 0; i < 4; i++) xv[i] = xs[kk][t0 + i];
#pragma unroll
            for (int j = 0; j < 6; j++) wv[j] = ws[kk][e0 + j];
#pragma unroll
            for (int i = 0; i < 4; i++)
#pragma unroll
                for (int j = 0; j < 6; j++) acc[i][j] += xv[i] * wv[j];
        }
    }
#pragma unroll
    for (int j = 0; j < 6; j++)
#pragma unroll
        for (int i = 0; i < 4; i++)
            g_logits[(size_t)(e0 + j) * T_TOK + tb + t0 + i] = acc[i][j];
}

// -------------------- per-expert top-512 + softmax --------------------------
// One block (256 threads) per expert. 3-stage radix select (12+12+8 bits) on
// monotone keys, exact threshold, ties broken by smallest index (jax top_k).
__global__ __launch_bounds__(256) void topk_kernel() {
    const int e = blockIdx.x;
    const float* lg = g_logits + (size_t)e * T_TOK;
    const int tid = threadIdx.x;

    __shared__ unsigned hist[4096];
    __shared__ unsigned csum[256];
    __shared__ int      eq_idx[256];
    __shared__ float    svals[CAP];
    __shared__ float    sred[256];
    __shared__ unsigned s_binA, s_cntA, s_binB, s_cntB, s_key;
    __shared__ unsigned s_pos, s_eqcnt;

    // ---- pass A: top 12 bits ----
    for (int i = tid; i < 4096; i += 256) hist[i] = 0;
    __syncthreads();
    for (int t = tid; t < T_TOK; t += 256) {
        unsigned k = fkey(lg[t]);
        atomicAdd(&hist[k >> 20], 1u);
    }
    __syncthreads();
    {
        unsigned s = 0;
#pragma unroll
        for (int j = 0; j < 16; j++) s += hist[tid * 16 + j];
        csum[tid] = s;
    }
    __syncthreads();
    if (tid == 0) {
        unsigned need = CAP, cum = 0;
        int chunk = 0;
        for (int c = 255; c >= 0; c--) {
            if (cum + csum[c] >= need) { chunk = c; break; }
            cum += csum[c];
        }
        int bsel = chunk * 16;
        for (int b = chunk * 16 + 15; b >= chunk * 16; b--) {
            if (cum + hist[b] >= need) { bsel = b; break; }
            cum += hist[b];
        }
        s_binA = (unsigned)bsel;
        s_cntA = cum;  // strictly above binA
    }
    __syncthreads();
    const unsigned binA = s_binA, cntA = s_cntA;

    // ---- pass B: middle 12 bits within binA ----
    for (int i = tid; i < 4096; i += 256) hist[i] = 0;
    __syncthreads();
    for (int t = tid; t < T_TOK; t += 256) {
        unsigned k = fkey(lg[t]);
        if ((k >> 20) == binA) atomicAdd(&hist[(k >> 8) & 0xFFFu], 1u);
    }
    __syncthreads();
    {
        unsigned s = 0;
#pragma unroll
        for (int j = 0; j < 16; j++) s += hist[tid * 16 + j];
        csum[tid] = s;
    }
    __syncthreads();
    if (tid == 0) {
        unsigned need = CAP - cntA, cum = 0;
        int chunk = 0;
        for (int c = 255; c >= 0; c--) {
            if (cum + csum[c] >= need) { chunk = c; break; }
            cum += csum[c];
        }
        int bsel = chunk * 16;
        for (int b = chunk * 16 + 15; b >= chunk * 16; b--) {
            if (cum + hist[b] >= need) { bsel = b; break; }
            cum += hist[b];
        }
        s_binB = (unsigned)bsel;
        s_cntB = cum;
    }
    __syncthreads();
    const unsigned binB = s_binB, cntB = s_cntB;
    const unsigned prefix = (binA << 12) | binB;

    // ---- pass C: low 8 bits within (binA,binB) ----
    for (int i = tid; i < 256; i += 256) hist[i] = 0;
    __syncthreads();
    for (int t = tid; t < T_TOK; t += 256) {
        unsigned k = fkey(lg[t]);
        if ((k >> 8) == prefix) atomicAdd(&hist[k & 0xFFu], 1u);
    }
    __syncthreads();
    if (tid == 0) {
        unsigned need = CAP - cntA - cntB, cum = 0;
        int bsel = 0;
        for (int b = 255; b >= 0; b--) {
            if (cum + hist[b] >= need) { bsel = b; break; }
            cum += hist[b];
        }
        s_key = (prefix << 8) | (unsigned)bsel;  // exact threshold key
        s_pos = 0;
        s_eqcnt = 0;
    }
    __syncthreads();
    const unsigned ukey = s_key;

    // ---- pass D: emit strictly-greater, collect equals ----
    for (int t = tid; t < T_TOK; t += 256) {
        float v = lg[t];
        unsigned k = fkey(v);
        if (k > ukey) {
            unsigned p = atomicAdd(&s_pos, 1u);
            g_idx[e * CAP + p] = t;
            svals[p] = v;
        } else if (k == ukey) {
            unsigned q = atomicAdd(&s_eqcnt, 1u);
            if (q < 256) eq_idx[q] = t;
        }
    }
    __syncthreads();
    if (tid == 0) {
        int ngt  = (int)s_pos;
        int need = CAP - ngt;
        int m    = (int)(s_eqcnt < 256u ? s_eqcnt : 256u);
        for (int i = 0; i < need; i++) {  // smallest indices first (tie rule)
            int best = 0x7fffffff, bj = -1;
            for (int j = 0; j < m; j++)
                if (eq_idx[j] < best) { best = eq_idx[j]; bj = j; }
            eq_idx[bj] = 0x7fffffff;
            g_idx[e * CAP + ngt + i] = best;
            svals[ngt + i] = lg[best];
        }
    }
    __syncthreads();

    // ---- softmax over the 512 selected values ----
    float mx = -3.4e38f;
    for (int i = tid; i < CAP; i += 256) mx = fmaxf(mx, svals[i]);
    sred[tid] = mx;
    __syncthreads();
    for (int o = 128; o > 0; o >>= 1) {
        if (tid < o) sred[tid] = fmaxf(sred[tid], sred[tid + o]);
        __syncthreads();
    }
    const float vmax = sred[0];
    __syncthreads();
    float sum = 0.f;
    for (int i = tid; i < CAP; i += 256) sum += expf(svals[i] - vmax);
    sred[tid] = sum;
    __syncthreads();
    for (int o = 128; o > 0; o >>= 1) {
        if (tid < o) sred[tid] += sred[tid + o];
        __syncthreads();
    }
    const float tot = sred[0];
    __syncthreads();
    for (int i = tid; i < CAP; i += 256)
        g_w[e * CAP + i] = expf(svals[i] - vmax) / tot;
}

// ------------------------------- gather ------------------------------------
__global__ __launch_bounds__(256) void gather_kernel(const float* __restrict__ x) {
    const int ec = blockIdx.x;                 // e*CAP + c
    const int t  = g_idx[ec];
    const float4* src = (const float4*)(x + (size_t)t * D_DIM);
    float4* dst = (float4*)(g_xg + (size_t)ec * D_DIM);
    dst[threadIdx.x] = src[threadIdx.x];       // 256 * float4 = 1024 floats
}

// --------------------- tiled fp32 GEMM (FFMA2 inner) ------------------------
// 128x128 block tile, 8x8 per thread, BK=16. IS_G2=false: xg@W1 + b1 -> gelu
// -> h.  IS_G2=true: h@W2 + b2, *w, atomic scatter into out.
template <bool IS_G2>
__global__ __launch_bounds__(256, 2) void moe_gemm(const float* __restrict__ Bw,
                                                   const float* __restrict__ bias_g,
                                                   float* __restrict__ out) {
    const int es   = blockIdx.z;            // e*S + s
    const int e    = es >> 2;
    const int s    = es & 3;
    const int row0 = blockIdx.y * 128;
    const int col0 = blockIdx.x * 128;
    const int NB   = IS_G2 ? K_DIM : M_DIM;  // B columns

    const float* A    = IS_G2 ? (g_h + (size_t)es * CAP * M_DIM)
                              : (g_xg + (size_t)e * CAP * D_DIM);
    const float* Bm   = Bw + (size_t)es * 1024 * NB;     // K-rows = 1024 both
    const float* bias = bias_g + (size_t)es * NB;

    __shared__ float As[16][132];   // [k][m], padded
    __shared__ float Bs[16][128];   // [k][n]

    const int tid = threadIdx.x;
    const int ty  = tid >> 4;       // 0..15 -> row group
    const int tx  = tid & 15;       // 0..15 -> col group

    unsigned long long acc[8][4];
#pragma unroll
    for (int i = 0; i < 8; i++)
#pragma unroll
        for (int j = 0; j < 4; j++) acc[i][j] = 0ull;

    float4 pa[2], pb[2];
    // prologue: chunk 0
#pragma unroll
    for (int i = 0; i < 2; i++) {
        int q = tid + 256 * i;
        int r = q >> 2, c = (q & 3) << 2;
        pa[i] = *(const float4*)(A + (size_t)(row0 + r) * 1024 + c);
        int rb = q >> 5, cb = (q & 31) << 2;
        pb[i] = *(const float4*)(Bm + (size_t)rb * NB + col0 + cb);
    }
#pragma unroll
    for (int i = 0; i < 2; i++) {
        int q = tid + 256 * i;
        int r = q >> 2, c = (q & 3) << 2;
        As[c + 0][r] = pa[i].x; As[c + 1][r] = pa[i].y;
        As[c + 2][r] = pa[i].z; As[c + 3][r] = pa[i].w;
        int rb = q >> 5, cb = (q & 31) << 2;
        *(float4*)&Bs[rb][cb] = pb[i];
    }
    __syncthreads();

    for (int kt = 0; kt < 64; kt++) {
        const int kb = (kt + 1) * 16;
        if (kt < 63) {
#pragma unroll
            for (int i = 0; i < 2; i++) {
                int q = tid + 256 * i;
                int r = q >> 2, c = (q & 3) << 2;
                pa[i] = *(const float4*)(A + (size_t)(row0 + r) * 1024 + kb + c);
                int rb = q >> 5, cb = (q & 31) << 2;
                pb[i] = *(const float4*)(Bm + (size_t)(kb + rb) * NB + col0 + cb);
            }
        }
#pragma unroll
        for (int kk = 0; kk < 16; kk++) {
            float4 a0 = *(const float4*)&As[kk][ty * 8];
            float4 a1 = *(const float4*)&As[kk][ty * 8 + 4];
            const unsigned long long* bp =
                (const unsigned long long*)&Bs[kk][tx * 8];
            unsigned long long b0 = bp[0], b1 = bp[1], b2 = bp[2], b3 = bp[3];
            float a[8] = {a0.x, a0.y, a0.z, a0.w, a1.x, a1.y, a1.z, a1.w};
#pragma unroll
            for (int i = 0; i < 8; i++) {
                unsigned long long ad = pack2(a[i], a[i]);
                acc[i][0] = fma2(ad, b0, acc[i][0]);
                acc[i][1] = fma2(ad, b1, acc[i][1]);
                acc[i][2] = fma2(ad, b2, acc[i][2]);
                acc[i][3] = fma2(ad, b3, acc[i][3]);
            }
        }
        __syncthreads();
        if (kt < 63) {
#pragma unroll
            for (int i = 0; i < 2; i++) {
                int q = tid + 256 * i;
                int r = q >> 2, c = (q & 3) << 2;
                As[c + 0][r] = pa[i].x; As[c + 1][r] = pa[i].y;
                As[c + 2][r] = pa[i].z; As[c + 3][r] = pa[i].w;
                int rb = q >> 5, cb = (q & 31) << 2;
                *(float4*)&Bs[rb][cb] = pb[i];
            }
            __syncthreads();
        }
    }

    if (!IS_G2) {
        float* C = g_h + (size_t)es * CAP * M_DIM;
#pragma unroll
        for (int i = 0; i < 8; i++) {
            size_t r = (size_t)(row0 + ty * 8 + i);
            float* crow = C + r * M_DIM;
#pragma unroll
            for (int j = 0; j < 4; j++) {
                int c = col0 + tx * 8 + 2 * j;
                crow[c]     = gelu_f(lo2(acc[i][j]) + bias[c]);
                crow[c + 1] = gelu_f(hi2(acc[i][j]) + bias[c + 1]);
            }
        }
    } else {
#pragma unroll
        for (int i = 0; i < 8; i++) {
            int r = row0 + ty * 8 + i;
            int tok = g_idx[e * CAP + r];
            float wgt = g_w[e * CAP + r];
            float* orow = out + (size_t)tok * D_DIM + s * K_DIM;
#pragma unroll
            for (int j = 0; j < 4; j++) {
                int c = col0 + tx * 8 + 2 * j;
                atomicAdd(orow + c,     (lo2(acc[i][j]) + bias[c])     * wgt);
                atomicAdd(orow + c + 1, (hi2(acc[i][j]) + bias[c + 1]) * wgt);
            }
        }
    }
}

// ------------------------------ launch -------------------------------------
extern "C" void kernel_launch(void* const* d_in, const int* in_sizes, int n_in,
                              void* d_out, int out_size) {
    const float* x  = (const float*)d_in[0];
    const float* Wr = (const float*)d_in[1];
    const float* W1 = (const float*)d_in[2];
    const float* b1 = (const float*)d_in[3];
    const float* W2 = (const float*)d_in[4];
    const float* b2 = (const float*)d_in[5];
    float* out = (float*)d_out;

    const int n4 = out_size / 4;
    zero_kernel<<<(n4 + 255) / 256, 256>>>((float4*)out, n4);
    router_kernel<<<T_TOK / 128, 256>>>(x, Wr);
    topk_kernel<<<E_EXP, 256>>>();
    gather_kernel<<<E_EXP * CAP, 256>>>(x);
    moe_gemm<false><<<dim3(M_DIM / 128, CAP / 128, E_EXP * S_SHARD), 256>>>(W1, b1, nullptr);
    moe_gemm<true><<<dim3(K_DIM / 128, CAP / 128, E_EXP * S_SHARD), 256>>>(W2, b2, out);
}

// round 3
// speedup vs baseline: 2.2451x; 2.2451x over previous
#include <cuda_runtime.h>
#include <cuda_bf16.h>
#include <cstdint>
#include <math.h>

// ---------------------------------------------------------------------------
// EfficientMoEMLPBlock — expert-choice MoE MLP on sm_103 (portable PTX only:
// no tcgen05 — ptxas target lacks the 'a' suffix).
//   E=48, S=4, D=1024, M=1024, K=D/S=256, T=16384, cap=512
// Round 3: ldmatrix + mma.sync.m16n8k16 bf16x3 GEMMs, cp.async 3-stage
//          pipeline, smem-staged epilogues, bulk reduce-add scatter.
// ---------------------------------------------------------------------------

#define T_TOK   16384
#define D_DIM   1024
#define E_EXP   48
#define S_SHARD 4
#define M_DIM   1024
#define K_DIM   256
#define CAP     512

typedef unsigned int uint32;
typedef unsigned long long uint64;

// ------------------------- scratch (device globals) ------------------------
__device__ float g_logits[(size_t)E_EXP * T_TOK];
__device__ int   g_idx[E_EXP * CAP];
__device__ float g_w[E_EXP * CAP];
__device__ __nv_bfloat16 g_xgh[(size_t)E_EXP * CAP * D_DIM];
__device__ __nv_bfloat16 g_xgl[(size_t)E_EXP * CAP * D_DIM];
__device__ __nv_bfloat16 g_w1h[(size_t)E_EXP * S_SHARD * M_DIM * D_DIM];  // [es][m][d]
__device__ __nv_bfloat16 g_w1l[(size_t)E_EXP * S_SHARD * M_DIM * D_DIM];
__device__ __nv_bfloat16 g_w2h[(size_t)E_EXP * S_SHARD * K_DIM * M_DIM];  // [es][k][m]
__device__ __nv_bfloat16 g_w2l[(size_t)E_EXP * S_SHARD * K_DIM * M_DIM];
__device__ __nv_bfloat16 g_hh[(size_t)E_EXP * S_SHARD * CAP * M_DIM];     // [es][c][m]
__device__ __nv_bfloat16 g_hl[(size_t)E_EXP * S_SHARD * CAP * M_DIM];

// ------------------------------- helpers -----------------------------------
__device__ __forceinline__ unsigned fkey(float f) {
    unsigned u = __float_as_uint(f);
    return (u & 0x80000000u) ? ~u : (u | 0x80000000u);
}
__device__ __forceinline__ float gelu_f(float v) {
    return 0.5f * v * (1.0f + erff(v * 0.70710678118654752440f));
}
__device__ __forceinline__ uint32 pack_bf(__nv_bfloat16 a, __nv_bfloat16 b) {
    return (uint32)__bfloat16_as_ushort(a) | ((uint32)__bfloat16_as_ushort(b) << 16);
}
__device__ __forceinline__ void split_bf(float v, __nv_bfloat16& h, __nv_bfloat16& l) {
    h = __float2bfloat16(v);
    l = __float2bfloat16(v - __bfloat162float(h));
}
__device__ __forceinline__ uint32 smem_u32(const void* p) {
    uint32 a;
    asm("{ .reg .u64 t; cvta.to.shared.u64 t, %1; cvt.u32.u64 %0, t; }" : "=r"(a) : "l"(p));
    return a;
}
// packed-swizzle smem layout: 2 logical rows per 128B physical row; 16B chunks
// swizzled so any 8 consecutive rows at fixed chunk hit 8 distinct banks.
__device__ __forceinline__ int phys(int r, int c) {
    return ((r >> 1) << 7) + (((((r & 1) << 2) | c) ^ ((r >> 1) & 7)) << 4);
}
__device__ __forceinline__ void cp_async16(uint32 saddr, const void* gaddr) {
    asm volatile("cp.async.cg.shared.global [%0], [%1], 16;"
                 :: "r"(saddr), "l"(gaddr) : "memory");
}
#define CP_COMMIT() asm volatile("cp.async.commit_group;" ::: "memory")
#define CP_WAIT(n)  asm volatile("cp.async.wait_group %0;" :: "n"(n) : "memory")

__device__ __forceinline__ void ldsm4(uint32* r, uint32 addr) {
    asm volatile("ldmatrix.sync.aligned.m8n8.x4.shared.b16 {%0,%1,%2,%3}, [%4];"
                 : "=r"(r[0]), "=r"(r[1]), "=r"(r[2]), "=r"(r[3]) : "r"(addr));
}
__device__ __forceinline__ void mma16816(float* c, const uint32* a, const uint32* b) {
    asm volatile(
        "mma.sync.aligned.m16n8k16.row.col.f32.bf16.bf16.f32 "
        "{%0,%1,%2,%3}, {%4,%5,%6,%7}, {%8,%9}, {%0,%1,%2,%3};"
        : "+f"(c[0]), "+f"(c[1]), "+f"(c[2]), "+f"(c[3])
        : "r"(a[0]), "r"(a[1]), "r"(a[2]), "r"(a[3]), "r"(b[0]), "r"(b[1]));
}
#define FENCE_ASYNC() asm volatile("fence.proxy.async.shared::cta;" ::: "memory")

// ------------------------------ zero out -----------------------------------
__global__ void zero_kernel(float4* __restrict__ p, int n4) {
    int i = blockIdx.x * blockDim.x + threadIdx.x;
    if (i < n4) p[i] = make_float4(0.f, 0.f, 0.f, 0.f);
}

// ------------------------- router logits [E][T] ----------------------------
__global__ __launch_bounds__(256) void router_kernel(const float* __restrict__ x,
                                                     const float* __restrict__ Wr) {
    __shared__ float xs[32][129];
    __shared__ float ws[32][49];
    const int tid = threadIdx.x;
    const int tb  = blockIdx.x * 128;
    const int t0  = (tid & 31) * 4;
    const int e0  = (tid >> 5) * 6;

    float acc[4][6];
#pragma unroll
    for (int i = 0; i < 4; i++)
#pragma unroll
        for (int j = 0; j < 6; j++) acc[i][j] = 0.f;

    for (int kb = 0; kb < D_DIM; kb += 32) {
        __syncthreads();
        for (int i = tid; i < 128 * 32; i += 256) {
            int r = i >> 5, c = i & 31;
            xs[c][r] = x[(size_t)(tb + r) * D_DIM + kb + c];
        }
        for (int i = tid; i < E_EXP * 32; i += 256) {
            int r = i >> 5, c = i & 31;
            ws[c][r] = Wr[(size_t)r * D_DIM + kb + c];
        }
        __syncthreads();
#pragma unroll 8
        for (int kk = 0; kk < 32; kk++) {
            float xv[4], wv[6];
#pragma unroll
            for (int i = 0; i < 4; i++) xv[i] = xs[kk][t0 + i];
#pragma unroll
            for (int j = 0; j < 6; j++) wv[j] = ws[kk][e0 + j];
#pragma unroll
            for (int i = 0; i < 4; i++)
#pragma unroll
                for (int j = 0; j < 6; j++) acc[i][j] += xv[i] * wv[j];
        }
    }
#pragma unroll
    for (int j = 0; j < 6; j++)
#pragma unroll
        for (int i = 0; i < 4; i++)
            g_logits[(size_t)(e0 + j) * T_TOK + tb + t0 + i] = acc[i][j];
}

// -------------------- per-expert top-512 + softmax --------------------------
__global__ __launch_bounds__(256) void topk_kernel() {
    const int e = blockIdx.x;
    const float* lg = g_logits + (size_t)e * T_TOK;
    const int tid = threadIdx.x;

    __shared__ unsigned hist[4096];
    __shared__ unsigned csum[256];
    __shared__ int      eq_idx[256];
    __shared__ float    svals[CAP];
    __shared__ float    sred[256];
    __shared__ unsigned s_binA, s_cntA, s_binB, s_cntB, s_key;
    __shared__ unsigned s_pos, s_eqcnt;

    for (int i = tid; i < 4096; i += 256) hist[i] = 0;
    __syncthreads();
    for (int t = tid; t < T_TOK; t += 256) {
        unsigned k = fkey(lg[t]);
        atomicAdd(&hist[k >> 20], 1u);
    }
    __syncthreads();
    {
        unsigned s = 0;
#pragma unroll
        for (int j = 0; j < 16; j++) s += hist[tid * 16 + j];
        csum[tid] = s;
    }
    __syncthreads();
    if (tid == 0) {
        unsigned need = CAP, cum = 0;
        int chunk = 0;
        for (int c = 255; c >= 0; c--) {
            if (cum + csum[c] >= need) { chunk = c; break; }
            cum += csum[c];
        }
        int bsel = chunk * 16;
        for (int b = chunk * 16 + 15; b >= chunk * 16; b--) {
            if (cum + hist[b] >= need) { bsel = b; break; }
            cum += hist[b];
        }
        s_binA = (unsigned)bsel;
        s_cntA = cum;
    }
    __syncthreads();
    const unsigned binA = s_binA, cntA = s_cntA;

    for (int i = tid; i < 4096; i += 256) hist[i] = 0;
    __syncthreads();
    for (int t = tid; t < T_TOK; t += 256) {
        unsigned k = fkey(lg[t]);
        if ((k >> 20) == binA) atomicAdd(&hist[(k >> 8) & 0xFFFu], 1u);
    }
    __syncthreads();
    {
        unsigned s = 0;
#pragma unroll
        for (int j = 0; j < 16; j++) s += hist[tid * 16 + j];
        csum[tid] = s;
    }
    __syncthreads();
    if (tid == 0) {
        unsigned need = CAP - cntA, cum = 0;
        int chunk = 0;
        for (int c = 255; c >= 0; c--) {
            if (cum + csum[c] >= need) { chunk = c; break; }
            cum += csum[c];
        }
        int bsel = chunk * 16;
        for (int b = chunk * 16 + 15; b >= chunk * 16; b--) {
            if (cum + hist[b] >= need) { bsel = b; break; }
            cum += hist[b];
        }
        s_binB = (unsigned)bsel;
        s_cntB = cum;
    }
    __syncthreads();
    const unsigned binB = s_binB, cntB = s_cntB;
    const unsigned prefix = (binA << 12) | binB;

    for (int i = tid; i < 256; i += 256) hist[i] = 0;
    __syncthreads();
    for (int t = tid; t < T_TOK; t += 256) {
        unsigned k = fkey(lg[t]);
        if ((k >> 8) == prefix) atomicAdd(&hist[k & 0xFFu], 1u);
    }
    __syncthreads();
    if (tid == 0) {
        unsigned need = CAP - cntA - cntB, cum = 0;
        int bsel = 0;
        for (int b = 255; b >= 0; b--) {
            if (cum + hist[b] >= need) { bsel = b; break; }
            cum += hist[b];
        }
        s_key = (prefix << 8) | (unsigned)bsel;
        s_pos = 0;
        s_eqcnt = 0;
    }
    __syncthreads();
    const unsigned ukey = s_key;

    for (int t = tid; t < T_TOK; t += 256) {
        float v = lg[t];
        unsigned k = fkey(v);
        if (k > ukey) {
            unsigned p = atomicAdd(&s_pos, 1u);
            g_idx[e * CAP + p] = t;
            svals[p] = v;
        } else if (k == ukey) {
            unsigned q = atomicAdd(&s_eqcnt, 1u);
            if (q < 256) eq_idx[q] = t;
        }
    }
    __syncthreads();
    if (tid == 0) {
        int ngt  = (int)s_pos;
        int need = CAP - ngt;
        int m    = (int)(s_eqcnt < 256u ? s_eqcnt : 256u);
        for (int i = 0; i < need; i++) {
            int best = 0x7fffffff, bj = -1;
            for (int j = 0; j < m; j++)
                if (eq_idx[j] < best) { best = eq_idx[j]; bj = j; }
            eq_idx[bj] = 0x7fffffff;
            g_idx[e * CAP + ngt + i] = best;
            svals[ngt + i] = lg[best];
        }
    }
    __syncthreads();

    float mx = -3.4e38f;
    for (int i = tid; i < CAP; i += 256) mx = fmaxf(mx, svals[i]);
    sred[tid] = mx;
    __syncthreads();
    for (int o = 128; o > 0; o >>= 1) {
        if (tid < o) sred[tid] = fmaxf(sred[tid], sred[tid + o]);
        __syncthreads();
    }
    const float vmax = sred[0];
    __syncthreads();
    float sum = 0.f;
    for (int i = tid; i < CAP; i += 256) sum += expf(svals[i] - vmax);
    sred[tid] = sum;
    __syncthreads();
    for (int o = 128; o > 0; o >>= 1) {
        if (tid < o) sred[tid] += sred[tid + o];
        __syncthreads();
    }
    const float tot = sred[0];
    __syncthreads();
    for (int i = tid; i < CAP; i += 256)
        g_w[e * CAP + i] = expf(svals[i] - vmax) / tot;
}

// --------------------- gather + bf16 hi/lo split ----------------------------
__global__ __launch_bounds__(256) void gather_kernel(const float* __restrict__ x) {
    const int ec = blockIdx.x;
    const int t  = g_idx[ec];
    float4 v = ((const float4*)(x + (size_t)t * D_DIM))[threadIdx.x];
    __nv_bfloat16 h0, h1, h2, h3, l0, l1, l2, l3;
    split_bf(v.x, h0, l0); split_bf(v.y, h1, l1);
    split_bf(v.z, h2, l2); split_bf(v.w, h3, l3);
    uint2 hh = make_uint2(pack_bf(h0, h1), pack_bf(h2, h3));
    uint2 ll = make_uint2(pack_bf(l0, l1), pack_bf(l2, l3));
    ((uint2*)(g_xgh + (size_t)ec * D_DIM))[threadIdx.x] = hh;
    ((uint2*)(g_xgl + (size_t)ec * D_DIM))[threadIdx.x] = ll;
}

// ------------- weight transpose + bf16 hi/lo split  [es][R][C] -> [es][C][R]
template <int WSEL>
__global__ __launch_bounds__(256) void conv_tr(const float* __restrict__ in, int R, int C) {
    __shared__ float t[32][33];
    const int es = blockIdx.z;
    const int c0 = blockIdx.x * 32, r0 = blockIdx.y * 32;
    const int tx = threadIdx.x & 31, ty = threadIdx.x >> 5;
    const float* ip = in + (size_t)es * R * C;
#pragma unroll
    for (int j = 0; j < 4; j++) {
        int r = ty + j * 8;
        t[r][tx] = ip[(size_t)(r0 + r) * C + c0 + tx];
    }
    __syncthreads();
    __nv_bfloat16* oh = (WSEL == 1) ? g_w1h : g_w2h;
    __nv_bfloat16* ol = (WSEL == 1) ? g_w1l : g_w2l;
    const size_t ob = (size_t)es * R * C;
#pragma unroll
    for (int j = 0; j < 4; j++) {
        int rr = ty + j * 8;
        float v = t[tx][rr];
        __nv_bfloat16 h, l;
        split_bf(v, h, l);
        size_t o = ob + (size_t)(c0 + rr) * R + r0 + tx;
        oh[o] = h;
        ol[o] = l;
    }
}

// -------------------- mma.sync bf16x3 GEMM  ---------------------------------
// CTA 128x128, 8 warps (2x4), warp tile 64x32, K=1024 in 32 chunks of 32.
// 3-stage cp.async pipeline; stage = Ah|Al|Bh|Bl, each 128x32 bf16 (8KB).
// smem: 3*32KB pipeline, reused as padded C tile (128x132 fp32) in epilogue.
#define STG_BYTES 32768
#define SMEM_GEMM (3 * STG_BYTES)
#define NCK 32

template <bool IS_G2>
__global__ __launch_bounds__(256, 2) void moe_mma(const float* __restrict__ bias_g,
                                                  float* __restrict__ out) {
    extern __shared__ char smem[];
    __shared__ float bias_s[128];
    const int es   = blockIdx.z, e = es >> 2, s = es & 3;
    const int row0 = blockIdx.y * 128;
    const int col0 = blockIdx.x * 128;
    const int tid  = threadIdx.x;
    const int lane = tid & 31, wid = tid >> 5;
    const int warpM = wid >> 2, warpN = wid & 3;
    const uint32 sb = smem_u32(smem);

    const __nv_bfloat16* Aph = (IS_G2 ? g_hh + (size_t)es * CAP * M_DIM
                                      : g_xgh + (size_t)e * CAP * D_DIM) + (size_t)row0 * 1024;
    const __nv_bfloat16* Apl = (IS_G2 ? g_hl + (size_t)es * CAP * M_DIM
                                      : g_xgl + (size_t)e * CAP * D_DIM) + (size_t)row0 * 1024;
    const __nv_bfloat16* Bph = (IS_G2 ? g_w2h + (size_t)es * K_DIM * M_DIM
                                      : g_w1h + (size_t)es * M_DIM * D_DIM) + (size_t)col0 * 1024;
    const __nv_bfloat16* Bpl = (IS_G2 ? g_w2l + (size_t)es * K_DIM * M_DIM
                                      : g_w1l + (size_t)es * M_DIM * D_DIM) + (size_t)col0 * 1024;
    const __nv_bfloat16* gb[4] = {Aph, Apl, Bph, Bpl};

    // per-thread load slots: 2048 16B-chunks per stage / 256 thr = 8
    uint32 soff[8];
    int    goff[8];
#pragma unroll
    for (int i = 0; i < 8; i++) {
        int idx = tid + i * 256;
        int w = idx & 511;
        int r = w >> 2, c = w & 3;
        soff[i] = (uint32)((i >> 1) * 8192 + phys(r, c));
        goff[i] = r * 1024 + c * 8;
    }

    float acc[4][4][4];
#pragma unroll
    for (int mi = 0; mi < 4; mi++)
#pragma unroll
        for (int ni = 0; ni < 4; ni++)
#pragma unroll
            for (int q = 0; q < 4; q++) acc[mi][ni][q] = 0.f;

    // prologue: stages 0,1
#pragma unroll
    for (int st = 0; st < 2; st++) {
        const int kb = st * 32;
#pragma unroll
        for (int i = 0; i < 8; i++)
            cp_async16(sb + st * STG_BYTES + soff[i], gb[i >> 1] + goff[i] + kb);
        CP_COMMIT();
    }

    for (int ck = 0; ck < NCK; ck++) {
        CP_WAIT(1);
        __syncthreads();
        if (ck + 2 < NCK) {
            const int st = (ck + 2) % 3;
            const int kb = (ck + 2) * 32;
#pragma unroll
            for (int i = 0; i < 8; i++)
                cp_async16(sb + st * STG_BYTES + soff[i], gb[i >> 1] + goff[i] + kb);
        }
        CP_COMMIT();

        const uint32 s0 = sb + (ck % 3) * STG_BYTES;
#pragma unroll
        for (int kh = 0; kh < 2; kh++) {
            uint32 Bh[2][4], Bl[2][4];
#pragma unroll
            for (int np = 0; np < 2; np++) {
                int nr = warpN * 32 + np * 16 + ((lane >> 4) << 3) + (lane & 7);
                int ch = kh * 2 + ((lane >> 3) & 1);
                int po = phys(nr, ch);
                ldsm4(Bh[np], s0 + 16384 + po);
                ldsm4(Bl[np], s0 + 24576 + po);
            }
#pragma unroll
            for (int mi = 0; mi < 4; mi++) {
                int ar = warpM * 64 + mi * 16 + (lane & 15);
                int ch = kh * 2 + (lane >> 4);
                int po = phys(ar, ch);
                uint32 Ah[4], Al[4];
                ldsm4(Ah, s0 + po);
                ldsm4(Al, s0 + 8192 + po);
#pragma unroll
                for (int ni = 0; ni < 4; ni++) {
                    const uint32* bh = &Bh[ni >> 1][(ni & 1) * 2];
                    const uint32* bl = &Bl[ni >> 1][(ni & 1) * 2];
                    mma16816(acc[mi][ni], Ah, bh);
                    mma16816(acc[mi][ni], Al, bh);
                    mma16816(acc[mi][ni], Ah, bl);
                }
            }
        }
    }

    CP_WAIT(0);
    __syncthreads();

    // ------------------------------ epilogue -------------------------------
    const int NB = IS_G2 ? K_DIM : M_DIM;
    if (tid < 128) bias_s[tid] = bias_g[(size_t)es * NB + col0 + tid];
    __syncthreads();

    float* Cs = (float*)smem;   // [128][132]
    if (!IS_G2) {
#pragma unroll
        for (int mi = 0; mi < 4; mi++)
#pragma unroll
            for (int ni = 0; ni < 4; ni++) {
                int r0 = warpM * 64 + mi * 16 + (lane >> 2);
                int c0 = warpN * 32 + ni * 8 + (lane & 3) * 2;
                Cs[r0 * 132 + c0]       = acc[mi][ni][0];
                Cs[r0 * 132 + c0 + 1]   = acc[mi][ni][1];
                Cs[(r0 + 8) * 132 + c0]     = acc[mi][ni][2];
                Cs[(r0 + 8) * 132 + c0 + 1] = acc[mi][ni][3];
            }
        __syncthreads();
        uint32* dh = (uint32*)g_hh;
        uint32* dl = (uint32*)g_hl;
        const size_t rowbase = (size_t)es * CAP + row0;
#pragma unroll 4
        for (int it = 0; it < 32; it++) {
            int idx = tid + it * 256;
            int r = idx >> 6, cp = idx & 63;
            float v0 = gelu_f(Cs[r * 132 + cp * 2]     + bias_s[cp * 2]);
            float v1 = gelu_f(Cs[r * 132 + cp * 2 + 1] + bias_s[cp * 2 + 1]);
            __nv_bfloat16 h0, h1, l0, l1;
            split_bf(v0, h0, l0);
            split_bf(v1, h1, l1);
            size_t di = (rowbase + r) * 512 + (col0 >> 1) + cp;
            dh[di] = pack_bf(h0, h1);
            dl[di] = pack_bf(l0, l1);
        }
    } else {
        // apply bias + routing weight while staging, then bulk reduce-add rows
        float wv[8];
#pragma unroll
        for (int mi = 0; mi < 4; mi++) {
            wv[mi * 2]     = g_w[e * CAP + row0 + warpM * 64 + mi * 16 + (lane >> 2)];
            wv[mi * 2 + 1] = g_w[e * CAP + row0 + warpM * 64 + mi * 16 + (lane >> 2) + 8];
        }
#pragma unroll
        for (int mi = 0; mi < 4; mi++)
#pragma unroll
            for (int ni = 0; ni < 4; ni++) {
                int r0 = warpM * 64 + mi * 16 + (lane >> 2);
                int c0 = warpN * 32 + ni * 8 + (lane & 3) * 2;
                Cs[r0 * 132 + c0]       = (acc[mi][ni][0] + bias_s[c0])     * wv[mi * 2];
                Cs[r0 * 132 + c0 + 1]   = (acc[mi][ni][1] + bias_s[c0 + 1]) * wv[mi * 2];
                Cs[(r0 + 8) * 132 + c0]     = (acc[mi][ni][2] + bias_s[c0])     * wv[mi * 2 + 1];
                Cs[(r0 + 8) * 132 + c0 + 1] = (acc[mi][ni][3] + bias_s[c0 + 1]) * wv[mi * 2 + 1];
            }
        __syncthreads();
        FENCE_ASYNC();
        if (tid < 128) {
            const int r = tid;
            const int tok = g_idx[e * CAP + row0 + r];
            float* gdst = out + (size_t)tok * D_DIM + s * K_DIM + col0;
            uint32 sa = sb + (uint32)r * 132 * 4;
            asm volatile(
                "cp.reduce.async.bulk.global.shared::cta.bulk_group.add.f32 [%0], [%1], %2;"
                :: "l"(gdst), "r"(sa), "r"(512u) : "memory");
            asm volatile("cp.async.bulk.commit_group;" ::: "memory");
            asm volatile("cp.async.bulk.wait_group 0;" ::: "memory");
        }
        __syncthreads();
    }
}

// ------------------------------ launch -------------------------------------
extern "C" void kernel_launch(void* const* d_in, const int* in_sizes, int n_in,
                              void* d_out, int out_size) {
    const float* x  = (const float*)d_in[0];
    const float* Wr = (const float*)d_in[1];
    const float* W1 = (const float*)d_in[2];
    const float* b1 = (const float*)d_in[3];
    const float* W2 = (const float*)d_in[4];
    const float* b2 = (const float*)d_in[5];
    float* out = (float*)d_out;

    cudaFuncSetAttribute(moe_mma<false>, cudaFuncAttributeMaxDynamicSharedMemorySize,
                         SMEM_GEMM);
    cudaFuncSetAttribute(moe_mma<true>, cudaFuncAttributeMaxDynamicSharedMemorySize,
                         SMEM_GEMM);

    const int n4 = out_size / 4;
    zero_kernel<<<(n4 + 255) / 256, 256>>>((float4*)out, n4);
    router_kernel<<<T_TOK / 128, 256>>>(x, Wr);
    topk_kernel<<<E_EXP, 256>>>();
    gather_kernel<<<E_EXP * CAP, 256>>>(x);
    conv_tr<1><<<dim3(32, 32, E_EXP * S_SHARD), 256>>>(W1, 1024, 1024);
    conv_tr<2><<<dim3(8, 32, E_EXP * S_SHARD), 256>>>(W2, 1024, 256);
    moe_mma<false><<<dim3(8, 4, E_EXP * S_SHARD), 256, SMEM_GEMM>>>(b1, nullptr);
    moe_mma<true><<<dim3(2, 4, E_EXP * S_SHARD), 256, SMEM_GEMM>>>(b2, out);
}

// round 7
// speedup vs baseline: 2.9972x; 1.3350x over previous
#include <cuda_runtime.h>
#include <cuda_bf16.h>
#include <cuda_fp16.h>
#include <cstdint>
#include <math.h>

// ---------------------------------------------------------------------------
// EfficientMoEMLPBlock — expert-choice MoE MLP on sm_103 (portable PTX only).
//   E=48, S=4, D=1024, M=1024, K=D/S=256, T=16384, cap=512
// Round 4: fp16 2-term GEMMs (A split exactly hi+lo, B rounded once):
//          y = (Ah+Al)·Bf  — error ~2^-12 from B only. 2 MMAs per product
//          instead of bf16x3's 3. cp.async 3-stage pipeline, mma.sync.
// ---------------------------------------------------------------------------

#define T_TOK   16384
#define D_DIM   1024
#define E_EXP   48
#define S_SHARD 4
#define M_DIM   1024
#define K_DIM   256
#define CAP     512

typedef unsigned int uint32;
typedef unsigned long long uint64;

// ------------------------- scratch (device globals) ------------------------
__device__ float g_logits[(size_t)E_EXP * T_TOK];
__device__ int   g_idx[E_EXP * CAP];
__device__ float g_w[E_EXP * CAP];
__device__ __half g_xgh[(size_t)E_EXP * CAP * D_DIM];
__device__ __half g_xgl[(size_t)E_EXP * CAP * D_DIM];
__device__ __half g_w1h[(size_t)E_EXP * S_SHARD * M_DIM * D_DIM];  // [es][m][d]
__device__ __half g_w2h[(size_t)E_EXP * S_SHARD * K_DIM * M_DIM];  // [es][k][m]
__device__ __half g_hh[(size_t)E_EXP * S_SHARD * CAP * M_DIM];     // [es][c][m]
__device__ __half g_hl[(size_t)E_EXP * S_SHARD * CAP * M_DIM];

// ------------------------------- helpers -----------------------------------
__device__ __forceinline__ unsigned fkey(float f) {
    unsigned u = __float_as_uint(f);
    return (u & 0x80000000u) ? ~u : (u | 0x80000000u);
}
__device__ __forceinline__ float gelu_f(float v) {
    return 0.5f * v * (1.0f + erff(v * 0.70710678118654752440f));
}
__device__ __forceinline__ uint32 pack_hf(__half a, __half b) {
    return (uint32)__half_as_ushort(a) | ((uint32)__half_as_ushort(b) << 16);
}
__device__ __forceinline__ void split_hf(float v, __half& h, __half& l) {
    h = __float2half_rn(v);
    l = __float2half_rn(v - __half2float(h));
}
__device__ __forceinline__ uint32 smem_u32(const void* p) {
    uint32 a;
    asm("{ .reg .u64 t; cvta.to.shared.u64 t, %1; cvt.u32.u64 %0, t; }" : "=r"(a) : "l"(p));
    return a;
}
// packed-swizzle smem layout: 2 logical rows (64B each) per 128B physical row;
// 16B chunks XOR-swizzled so 8 consecutive rows at fixed chunk are conflict-free.
__device__ __forceinline__ int phys(int r, int c) {
    return ((r >> 1) << 7) + (((((r & 1) << 2) | c) ^ ((r >> 1) & 7)) << 4);
}
__device__ __forceinline__ void cp_async16(uint32 saddr, const void* gaddr) {
    asm volatile("cp.async.cg.shared.global [%0], [%1], 16;"
                 :: "r"(saddr), "l"(gaddr) : "memory");
}
#define CP_COMMIT() asm volatile("cp.async.commit_group;" ::: "memory")
#define CP_WAIT(n)  asm volatile("cp.async.wait_group %0;" :: "n"(n) : "memory")

__device__ __forceinline__ void ldsm4(uint32* r, uint32 addr) {
    asm volatile("ldmatrix.sync.aligned.m8n8.x4.shared.b16 {%0,%1,%2,%3}, [%4];"
                 : "=r"(r[0]), "=r"(r[1]), "=r"(r[2]), "=r"(r[3]) : "r"(addr));
}
__device__ __forceinline__ void mma16816(float* c, const uint32* a, const uint32* b) {
    asm volatile(
        "mma.sync.aligned.m16n8k16.row.col.f32.f16.f16.f32 "
        "{%0,%1,%2,%3}, {%4,%5,%6,%7}, {%8,%9}, {%0,%1,%2,%3};"
        : "+f"(c[0]), "+f"(c[1]), "+f"(c[2]), "+f"(c[3])
        : "r"(a[0]), "r"(a[1]), "r"(a[2]), "r"(a[3]), "r"(b[0]), "r"(b[1]));
}
#define FENCE_ASYNC() asm volatile("fence.proxy.async.shared::cta;" ::: "memory")

// ------------------------------ zero out -----------------------------------
__global__ void zero_kernel(float4* __restrict__ p, int n4) {
    int i = blockIdx.x * blockDim.x + threadIdx.x;
    if (i < n4) p[i] = make_float4(0.f, 0.f, 0.f, 0.f);
}

// ------------------------- router logits [E][T] ----------------------------
__global__ __launch_bounds__(256) void router_kernel(const float* __restrict__ x,
                                                     const float* __restrict__ Wr) {
    __shared__ float xs[32][129];
    __shared__ float ws[32][49];
    const int tid = threadIdx.x;
    const int tb  = blockIdx.x * 128;
    const int t0  = (tid & 31) * 4;
    const int e0  = (tid >> 5) * 6;

    float acc[4][6];
#pragma unroll
    for (int i = 0; i < 4; i++)
#pragma unroll
        for (int j = 0; j < 6; j++) acc[i][j] = 0.f;

    for (int kb = 0; kb < D_DIM; kb += 32) {
        __syncthreads();
        for (int i = tid; i < 128 * 32; i += 256) {
            int r = i >> 5, c = i & 31;
            xs[c][r] = x[(size_t)(tb + r) * D_DIM + kb + c];
        }
        for (int i = tid; i < E_EXP * 32; i += 256) {
            int r = i >> 5, c = i & 31;
            ws[c][r] = Wr[(size_t)r * D_DIM + kb + c];
        }
        __syncthreads();
#pragma unroll 8
        for (int kk = 0; kk < 32; kk++) {
            float xv[4], wv[6];
#pragma unroll
            for (int i = 0; i < 4; i++) xv[i] = xs[kk][t0 + i];
#pragma unroll
            for (int j = 0; j < 6; j++) wv[j] = ws[kk][e0 + j];
#pragma unroll
            for (int i = 0; i < 4; i++)
#pragma unroll
                for (int j = 0; j < 6; j++) acc[i][j] += xv[i] * wv[j];
        }
    }
#pragma unroll
    for (int j = 0; j < 6; j++)
#pragma unroll
        for (int i = 0; i < 4; i++)
            g_logits[(size_t)(e0 + j) * T_TOK + tb + t0 + i] = acc[i][j];
}

// -------------------- per-expert top-512 + softmax --------------------------
__global__ __launch_bounds__(256) void topk_kernel() {
    const int e = blockIdx.x;
    const float* lg = g_logits + (size_t)e * T_TOK;
    const int tid = threadIdx.x;

    __shared__ unsigned hist[4096];
    __shared__ unsigned csum[256];
    __shared__ int      eq_idx[256];
    __shared__ float    svals[CAP];
    __shared__ float    sred[256];
    __shared__ unsigned s_binA, s_cntA, s_binB, s_cntB, s_key;
    __shared__ unsigned s_pos, s_eqcnt;

    for (int i = tid; i < 4096; i += 256) hist[i] = 0;
    __syncthreads();
    for (int t = tid; t < T_TOK; t += 256) {
        unsigned k = fkey(lg[t]);
        atomicAdd(&hist[k >> 20], 1u);
    }
    __syncthreads();
    {
        unsigned s = 0;
#pragma unroll
        for (int j = 0; j < 16; j++) s += hist[tid * 16 + j];
        csum[tid] = s;
    }
    __syncthreads();
    if (tid == 0) {
        unsigned need = CAP, cum = 0;
        int chunk = 0;
        for (int c = 255; c >= 0; c--) {
            if (cum + csum[c] >= need) { chunk = c; break; }
            cum += csum[c];
        }
        int bsel = chunk * 16;
        for (int b = chunk * 16 + 15; b >= chunk * 16; b--) {
            if (cum + hist[b] >= need) { bsel = b; break; }
            cum += hist[b];
        }
        s_binA = (unsigned)bsel;
        s_cntA = cum;
    }
    __syncthreads();
    const unsigned binA = s_binA, cntA = s_cntA;

    for (int i = tid; i < 4096; i += 256) hist[i] = 0;
    __syncthreads();
    for (int t = tid; t < T_TOK; t += 256) {
        unsigned k = fkey(lg[t]);
        if ((k >> 20) == binA) atomicAdd(&hist[(k >> 8) & 0xFFFu], 1u);
    }
    __syncthreads();
    {
        unsigned s = 0;
#pragma unroll
        for (int j = 0; j < 16; j++) s += hist[tid * 16 + j];
        csum[tid] = s;
    }
    __syncthreads();
    if (tid == 0) {
        unsigned need = CAP - cntA, cum = 0;
        int chunk = 0;
        for (int c = 255; c >= 0; c--) {
            if (cum + csum[c] >= need) { chunk = c; break; }
            cum += csum[c];
        }
        int bsel = chunk * 16;
        for (int b = chunk * 16 + 15; b >= chunk * 16; b--) {
            if (cum + hist[b] >= need) { bsel = b; break; }
            cum += hist[b];
        }
        s_binB = (unsigned)bsel;
        s_cntB = cum;
    }
    __syncthreads();
    const unsigned binB = s_binB, cntB = s_cntB;
    const unsigned prefix = (binA << 12) | binB;

    for (int i = tid; i < 256; i += 256) hist[i] = 0;
    __syncthreads();
    for (int t = tid; t < T_TOK; t += 256) {
        unsigned k = fkey(lg[t]);
        if ((k >> 8) == prefix) atomicAdd(&hist[k & 0xFFu], 1u);
    }
    __syncthreads();
    if (tid == 0) {
        unsigned need = CAP - cntA - cntB, cum = 0;
        int bsel = 0;
        for (int b = 255; b >= 0; b--) {
            if (cum + hist[b] >= need) { bsel = b; break; }
            cum += hist[b];
        }
        s_key = (prefix << 8) | (unsigned)bsel;
        s_pos = 0;
        s_eqcnt = 0;
    }
    __syncthreads();
    const unsigned ukey = s_key;

    for (int t = tid; t < T_TOK; t += 256) {
        float v = lg[t];
        unsigned k = fkey(v);
        if (k > ukey) {
            unsigned p = atomicAdd(&s_pos, 1u);
            g_idx[e * CAP + p] = t;
            svals[p] = v;
        } else if (k == ukey) {
            unsigned q = atomicAdd(&s_eqcnt, 1u);
            if (q < 256) eq_idx[q] = t;
        }
    }
    __syncthreads();
    if (tid == 0) {
        int ngt  = (int)s_pos;
        int need = CAP - ngt;
        int m    = (int)(s_eqcnt < 256u ? s_eqcnt : 256u);
        for (int i = 0; i < need; i++) {
            int best = 0x7fffffff, bj = -1;
            for (int j = 0; j < m; j++)
                if (eq_idx[j] < best) { best = eq_idx[j]; bj = j; }
            eq_idx[bj] = 0x7fffffff;
            g_idx[e * CAP + ngt + i] = best;
            svals[ngt + i] = lg[best];
        }
    }
    __syncthreads();

    float mx = -3.4e38f;
    for (int i = tid; i < CAP; i += 256) mx = fmaxf(mx, svals[i]);
    sred[tid] = mx;
    __syncthreads();
    for (int o = 128; o > 0; o >>= 1) {
        if (tid < o) sred[tid] = fmaxf(sred[tid], sred[tid + o]);
        __syncthreads();
    }
    const float vmax = sred[0];
    __syncthreads();
    float sum = 0.f;
    for (int i = tid; i < CAP; i += 256) sum += expf(svals[i] - vmax);
    sred[tid] = sum;
    __syncthreads();
    for (int o = 128; o > 0; o >>= 1) {
        if (tid < o) sred[tid] += sred[tid + o];
        __syncthreads();
    }
    const float tot = sred[0];
    __syncthreads();
    for (int i = tid; i < CAP; i += 256)
        g_w[e * CAP + i] = expf(svals[i] - vmax) / tot;
}

// --------------------- gather + fp16 hi/lo split ----------------------------
__global__ __launch_bounds__(256) void gather_kernel(const float* __restrict__ x) {
    const int ec = blockIdx.x;
    const int t  = g_idx[ec];
    float4 v = ((const float4*)(x + (size_t)t * D_DIM))[threadIdx.x];
    __half h0, h1, h2, h3, l0, l1, l2, l3;
    split_hf(v.x, h0, l0); split_hf(v.y, h1, l1);
    split_hf(v.z, h2, l2); split_hf(v.w, h3, l3);
    uint2 hh = make_uint2(pack_hf(h0, h1), pack_hf(h2, h3));
    uint2 ll = make_uint2(pack_hf(l0, l1), pack_hf(l2, l3));
    ((uint2*)(g_xgh + (size_t)ec * D_DIM))[threadIdx.x] = hh;
    ((uint2*)(g_xgl + (size_t)ec * D_DIM))[threadIdx.x] = ll;
}

// ---- fused weight transpose + fp16 round  [es][R][C] -> [es][C][R] ---------
// blockIdx.x < 32: W1 (C=1024); else W2 (C=256). R=1024 both.
__global__ __launch_bounds__(256) void conv_kernel(const float* __restrict__ W1,
                                                   const float* __restrict__ W2) {
    __shared__ float t[32][33];
    const bool is1 = blockIdx.x < 32;
    const int bx = is1 ? blockIdx.x : blockIdx.x - 32;
    const int es = blockIdx.z;
    const int C  = is1 ? 1024 : 256;
    const float* in = is1 ? W1 : W2;
    __half* outp = is1 ? g_w1h : g_w2h;

    const int c0 = bx * 32, r0 = blockIdx.y * 32;
    const int tx = threadIdx.x & 31, ty = threadIdx.x >> 5;
    const float* ip = in + (size_t)es * 1024 * C;
#pragma unroll
    for (int j = 0; j < 4; j++) {
        int r = ty + j * 8;
        t[r][tx] = ip[(size_t)(r0 + r) * C + c0 + tx];
    }
    __syncthreads();
    const size_t ob = (size_t)es * 1024 * C;
#pragma unroll
    for (int j = 0; j < 4; j++) {
        int rr = ty + j * 8;
        outp[ob + (size_t)(c0 + rr) * 1024 + r0 + tx] = __float2half_rn(t[tx][rr]);
    }
}

// -------------------- mma.sync fp16 2-term GEMM -----------------------------
// CTA 128x128, 8 warps (2x4), warp tile 64x32, K=1024 in 32 chunks of 32.
// 3-stage cp.async pipeline; stage = Ah|Al|Bf, each 128x32 fp16 (8KB) = 24KB.
// smem reused as padded C tile (128x132 fp32) in epilogue.
#define STG_BYTES 24576
#define SMEM_GEMM (3 * STG_BYTES)
#define NCK 32

template <bool IS_G2>
__global__ __launch_bounds__(256, 2) void moe_mma(const float* __restrict__ bias_g,
                                                  float* __restrict__ out) {
    extern __shared__ char smem[];
    __shared__ float bias_s[128];
    const int es   = blockIdx.z, e = es >> 2, s = es & 3;
    const int row0 = blockIdx.y * 128;
    const int col0 = blockIdx.x * 128;
    const int tid  = threadIdx.x;
    const int lane = tid & 31, wid = tid >> 5;
    const int warpM = wid >> 2, warpN = wid & 3;
    const uint32 sb = smem_u32(smem);

    const __half* Aph = (IS_G2 ? g_hh + (size_t)es * CAP * M_DIM
                               : g_xgh + (size_t)e * CAP * D_DIM) + (size_t)row0 * 1024;
    const __half* Apl = (IS_G2 ? g_hl + (size_t)es * CAP * M_DIM
                               : g_xgl + (size_t)e * CAP * D_DIM) + (size_t)row0 * 1024;
    const __half* Bpf = (IS_G2 ? g_w2h + (size_t)es * K_DIM * M_DIM
                               : g_w1h + (size_t)es * M_DIM * D_DIM) + (size_t)col0 * 1024;

    // per-thread load slots: (1024 A chunks + 512 B chunks) / 256 thr = 6
    uint32 soff[6];
    const __half* gp[6];
#pragma unroll
    for (int i = 0; i < 6; i++) {
        int idx = tid + i * 256;
        int w = idx & 511;
        int r = w >> 2, c = w & 3;
        if (i < 4) {
            int plane = idx >> 9;  // 0 = Ah, 1 = Al
            soff[i] = (uint32)(plane * 8192 + phys(r, c));
            gp[i] = (plane ? Apl : Aph) + r * 1024 + c * 8;
        } else {
            soff[i] = (uint32)(16384 + phys(r, c));
            gp[i] = Bpf + r * 1024 + c * 8;
        }
    }

    float acc[4][4][4];
#pragma unroll
    for (int mi = 0; mi < 4; mi++)
#pragma unroll
        for (int ni = 0; ni < 4; ni++)
#pragma unroll
            for (int q = 0; q < 4; q++) acc[mi][ni][q] = 0.f;

    // prologue: stages 0,1
#pragma unroll
    for (int st = 0; st < 2; st++) {
        const int kb = st * 32;
#pragma unroll
        for (int i = 0; i < 6; i++)
            cp_async16(sb + st * STG_BYTES + soff[i], gp[i] + kb);
        CP_COMMIT();
    }

    for (int ck = 0; ck < NCK; ck++) {
        CP_WAIT(1);
        __syncthreads();
        if (ck + 2 < NCK) {
            const int st = (ck + 2) % 3;
            const int kb = (ck + 2) * 32;
#pragma unroll
            for (int i = 0; i < 6; i++)
                cp_async16(sb + st * STG_BYTES + soff[i], gp[i] + kb);
        }
        CP_COMMIT();

        const uint32 s0 = sb + (ck % 3) * STG_BYTES;
#pragma unroll
        for (int kh = 0; kh < 2; kh++) {
            uint32 Bf[2][4];
#pragma unroll
            for (int np = 0; np < 2; np++) {
                int nr = warpN * 32 + np * 16 + ((lane >> 4) << 3) + (lane & 7);
                int ch = kh * 2 + ((lane >> 3) & 1);
                ldsm4(Bf[np], s0 + 16384 + phys(nr, ch));
            }
#pragma unroll
            for (int mi = 0; mi < 4; mi++) {
                int ar = warpM * 64 + mi * 16 + (lane & 15);
                int ch = kh * 2 + (lane >> 4);
                int po = phys(ar, ch);
                uint32 Ah[4], Al[4];
                ldsm4(Ah, s0 + po);
                ldsm4(Al, s0 + 8192 + po);
#pragma unroll
                for (int ni = 0; ni < 4; ni++) {
                    const uint32* bf = &Bf[ni >> 1][(ni & 1) * 2];
                    mma16816(acc[mi][ni], Ah, bf);
                    mma16816(acc[mi][ni], Al, bf);
                }
            }
        }
    }

    CP_WAIT(0);
    __syncthreads();

    // ------------------------------ epilogue -------------------------------
    const int NB = IS_G2 ? K_DIM : M_DIM;
    if (tid < 128) bias_s[tid] = bias_g[(size_t)es * NB + col0 + tid];
    __syncthreads();

    float* Cs = (float*)smem;   // [128][132]
    if (!IS_G2) {
#pragma unroll
        for (int mi = 0; mi < 4; mi++)
#pragma unroll
            for (int ni = 0; ni < 4; ni++) {
                int r0 = warpM * 64 + mi * 16 + (lane >> 2);
                int c0 = warpN * 32 + ni * 8 + (lane & 3) * 2;
                Cs[r0 * 132 + c0]       = acc[mi][ni][0];
                Cs[r0 * 132 + c0 + 1]   = acc[mi][ni][1];
                Cs[(r0 + 8) * 132 + c0]     = acc[mi][ni][2];
                Cs[(r0 + 8) * 132 + c0 + 1] = acc[mi][ni][3];
            }
        __syncthreads();
        uint32* dh = (uint32*)g_hh;
        uint32* dl = (uint32*)g_hl;
        const size_t rowbase = (size_t)es * CAP + row0;
#pragma unroll 4
        for (int it = 0; it < 32; it++) {
            int idx = tid + it * 256;
            int r = idx >> 6, cp = idx & 63;
            float v0 = gelu_f(Cs[r * 132 + cp * 2]     + bias_s[cp * 2]);
            float v1 = gelu_f(Cs[r * 132 + cp * 2 + 1] + bias_s[cp * 2 + 1]);
            __half h0, h1, l0, l1;
            split_hf(v0, h0, l0);
            split_hf(v1, h1, l1);
            size_t di = (rowbase + r) * 512 + (col0 >> 1) + cp;
            dh[di] = pack_hf(h0, h1);
            dl[di] = pack_hf(l0, l1);
        }
    } else {
        // apply bias + routing weight while staging, then bulk reduce-add rows
        float wv[8];
#pragma unroll
        for (int mi = 0; mi < 4; mi++) {
            wv[mi * 2]     = g_w[e * CAP + row0 + warpM * 64 + mi * 16 + (lane >> 2)];
            wv[mi * 2 + 1] = g_w[e * CAP + row0 + warpM * 64 + mi * 16 + (lane >> 2) + 8];
        }
#pragma unroll
        for (int mi = 0; mi < 4; mi++)
#pragma unroll
            for (int ni = 0; ni < 4; ni++) {
                int r0 = warpM * 64 + mi * 16 + (lane >> 2);
                int c0 = warpN * 32 + ni * 8 + (lane & 3) * 2;
                Cs[r0 * 132 + c0]       = (acc[mi][ni][0] + bias_s[c0])     * wv[mi * 2];
                Cs[r0 * 132 + c0 + 1]   = (acc[mi][ni][1] + bias_s[c0 + 1]) * wv[mi * 2];
                Cs[(r0 + 8) * 132 + c0]     = (acc[mi][ni][2] + bias_s[c0])     * wv[mi * 2 + 1];
                Cs[(r0 + 8) * 132 + c0 + 1] = (acc[mi][ni][3] + bias_s[c0 + 1]) * wv[mi * 2 + 1];
            }
        __syncthreads();
        FENCE_ASYNC();
        if (tid < 128) {
            const int r = tid;
            const int tok = g_idx[e * CAP + row0 + r];
            float* gdst = out + (size_t)tok * D_DIM + s * K_DIM + col0;
            uint32 sa = sb + (uint32)r * 132 * 4;
            asm volatile(
                "cp.reduce.async.bulk.global.shared::cta.bulk_group.add.f32 [%0], [%1], %2;"
                :: "l"(gdst), "r"(sa), "r"(512u) : "memory");
            asm volatile("cp.async.bulk.commit_group;" ::: "memory");
            asm volatile("cp.async.bulk.wait_group 0;" ::: "memory");
        }
        __syncthreads();
    }
}

// ------------------------------ launch -------------------------------------
extern "C" void kernel_launch(void* const* d_in, const int* in_sizes, int n_in,
                              void* d_out, int out_size) {
    const float* x  = (const float*)d_in[0];
    const float* Wr = (const float*)d_in[1];
    const float* W1 = (const float*)d_in[2];
    const float* b1 = (const float*)d_in[3];
    const float* W2 = (const float*)d_in[4];
    const float* b2 = (const float*)d_in[5];
    float* out = (float*)d_out;

    cudaFuncSetAttribute(moe_mma<false>, cudaFuncAttributeMaxDynamicSharedMemorySize,
                         SMEM_GEMM);
    cudaFuncSetAttribute(moe_mma<true>, cudaFuncAttributeMaxDynamicSharedMemorySize,
                         SMEM_GEMM);

    const int n4 = out_size / 4;
    zero_kernel<<<(n4 + 255) / 256, 256>>>((float4*)out, n4);            // launch 0
    router_kernel<<<T_TOK / 128, 256>>>(x, Wr);                          // launch 1
    topk_kernel<<<E_EXP, 256>>>();                                       // launch 2
    gather_kernel<<<E_EXP * CAP, 256>>>(x);                              // launch 3
    conv_kernel<<<dim3(40, 32, E_EXP * S_SHARD), 256>>>(W1, W2);         // launch 4
    moe_mma<false><<<dim3(8, 4, E_EXP * S_SHARD), 256, SMEM_GEMM>>>(b1, nullptr);  // 5
    moe_mma<true><<<dim3(2, 4, E_EXP * S_SHARD), 256, SMEM_GEMM>>>(b2, out);       // 6
}